// round 9
// baseline (speedup 1.0000x reference)
#include <cuda_runtime.h>
#include <math.h>
#include <stdint.h>

#define B   32
#define S   128
#define T   128
#define E   256
#define H   512
#define VT  16000

// ---------------------------------------------------------------------------
__device__ float g_enc_gi [B * S * 3 * H];
__device__ float g_dec_giy[B * T * 3 * H];
__device__ float g_enc_out[B * S * H];
__device__ float g_enc_proj[B * S * H];
__device__ float g_dec_out[B * T * H];
__device__ float g_h[2][B * H];
__device__ float g_hq[B * H];
__device__ float g_scores[B * S];
__device__ float g_ctx[B * H];
__device__ unsigned g_flags[128];

__device__ __forceinline__ float sigf(float x) { return 1.f / (1.f + expf(-x)); }
__device__ __forceinline__ float tanh_fast(float x) {
    float y; asm("tanh.approx.f32 %0, %1;" : "=f"(y) : "f"(x)); return y;
}
__device__ __forceinline__ uint32_t f2tf32(float x) {
    uint32_t u; asm("cvt.rna.tf32.f32 %0, %1;" : "=r"(u) : "f"(x)); return u;
}

// Atomic-free grid barrier: per-CTA epoch flags, parallel polling.
// No LTS atomic serialization (the killer with 128 CTAs on one counter).
__device__ __forceinline__ void flag_bar(unsigned& epoch) {
    epoch++;
    __syncthreads();
    if (threadIdx.x == 0)
        asm volatile("st.release.gpu.u32 [%0], %1;"
                     :: "l"(&g_flags[blockIdx.x]), "r"(epoch) : "memory");
    if (threadIdx.x < 128) {
        unsigned v;
        do {
            asm volatile("ld.acquire.gpu.u32 %0, [%1];"
                         : "=r"(v) : "l"(&g_flags[threadIdx.x]) : "memory");
        } while (v < epoch);
    }
    __syncthreads();
}

// ---------------------------------------------------------------------------
// TF32 tensor-core GEMM
// ---------------------------------------------------------------------------
#define KT   32
#define LDS_ 36
#define BUFE (128 * LDS_)

__global__ void __launch_bounds__(256, 2) gemm_tf32(
    const float* __restrict__ A, int lda, const int* __restrict__ idx,
    const float* __restrict__ W, int ldw,
    const float* __restrict__ bias,
    float* __restrict__ out, int N, int K)
{
    extern __shared__ uint32_t smem_u[];
    uint32_t* As = smem_u;
    uint32_t* Bs = smem_u + 2 * BUFE;

    const int tid = threadIdx.x;
    const int m0 = blockIdx.y * 128, n0 = blockIdx.x * 128;
    const int warp = tid >> 5, lane = tid & 31;
    const int gid = lane >> 2, tig = lane & 3;
    const int wm = warp >> 1, wn = warp & 1;

    const int lrow = tid >> 3, lk = (tid & 7) * 4;
    const float* aptr[4];
    const float* bptr[4];
#pragma unroll
    for (int i = 0; i < 4; i++) {
        int m = m0 + lrow + i * 32;
        int r = idx ? idx[m] : m;
        aptr[i] = A + (size_t)r * lda + lk;
        bptr[i] = W + (size_t)(n0 + lrow + i * 32) * ldw + lk;
    }
    const int sst = lrow * LDS_ + lk;

    float acc[2][8][4];
#pragma unroll
    for (int mt = 0; mt < 2; mt++)
#pragma unroll
        for (int nt = 0; nt < 8; nt++)
#pragma unroll
            for (int c = 0; c < 4; c++) acc[mt][nt][c] = 0.f;

    const int nk = K / KT;
    float4 av[4], bv[4];

#pragma unroll
    for (int i = 0; i < 4; i++) {
        av[i] = *(const float4*)(aptr[i]);
        bv[i] = *(const float4*)(bptr[i]);
    }
#pragma unroll
    for (int i = 0; i < 4; i++) {
        uint32_t* a = As + sst + i * 32 * LDS_;
        a[0] = f2tf32(av[i].x); a[1] = f2tf32(av[i].y);
        a[2] = f2tf32(av[i].z); a[3] = f2tf32(av[i].w);
        uint32_t* b = Bs + sst + i * 32 * LDS_;
        b[0] = f2tf32(bv[i].x); b[1] = f2tf32(bv[i].y);
        b[2] = f2tf32(bv[i].z); b[3] = f2tf32(bv[i].w);
    }
    __syncthreads();

    for (int kt = 0; kt < nk; kt++) {
        if (kt + 1 < nk) {
            const int off = (kt + 1) * KT;
#pragma unroll
            for (int i = 0; i < 4; i++) {
                av[i] = *(const float4*)(aptr[i] + off);
                bv[i] = *(const float4*)(bptr[i] + off);
            }
        }

        const uint32_t* Ab = As + (kt & 1) * BUFE + wm * 32 * LDS_;
        const uint32_t* Bb = Bs + (kt & 1) * BUFE + wn * 64 * LDS_;
#pragma unroll
        for (int k8 = 0; k8 < 4; k8++) {
            const int kc = k8 * 8 + tig;
            uint32_t af[2][4], bf[8][2];
#pragma unroll
            for (int mt = 0; mt < 2; mt++) {
                const uint32_t* p = Ab + (mt * 16 + gid) * LDS_ + kc;
                af[mt][0] = p[0];
                af[mt][1] = p[8 * LDS_];
                af[mt][2] = p[4];
                af[mt][3] = p[8 * LDS_ + 4];
            }
#pragma unroll
            for (int nt = 0; nt < 8; nt++) {
                const uint32_t* p = Bb + (nt * 8 + gid) * LDS_ + kc;
                bf[nt][0] = p[0];
                bf[nt][1] = p[4];
            }
#pragma unroll
            for (int mt = 0; mt < 2; mt++)
#pragma unroll
                for (int nt = 0; nt < 8; nt++) {
                    float* c = acc[mt][nt];
                    asm volatile(
                        "mma.sync.aligned.m16n8k8.row.col.f32.tf32.tf32.f32 "
                        "{%0,%1,%2,%3}, {%4,%5,%6,%7}, {%8,%9}, {%0,%1,%2,%3};"
                        : "+f"(c[0]), "+f"(c[1]), "+f"(c[2]), "+f"(c[3])
                        : "r"(af[mt][0]), "r"(af[mt][1]), "r"(af[mt][2]), "r"(af[mt][3]),
                          "r"(bf[nt][0]), "r"(bf[nt][1]));
                }
        }

        if (kt + 1 < nk) {
            const int bsel = (kt + 1) & 1;
#pragma unroll
            for (int i = 0; i < 4; i++) {
                uint32_t* a = As + bsel * BUFE + sst + i * 32 * LDS_;
                a[0] = f2tf32(av[i].x); a[1] = f2tf32(av[i].y);
                a[2] = f2tf32(av[i].z); a[3] = f2tf32(av[i].w);
                uint32_t* b = Bs + bsel * BUFE + sst + i * 32 * LDS_;
                b[0] = f2tf32(bv[i].x); b[1] = f2tf32(bv[i].y);
                b[2] = f2tf32(bv[i].z); b[3] = f2tf32(bv[i].w);
            }
            __syncthreads();
        }
    }

#pragma unroll
    for (int mt = 0; mt < 2; mt++) {
        const int m = m0 + wm * 32 + mt * 16 + gid;
#pragma unroll
        for (int nt = 0; nt < 8; nt++) {
            const int n = n0 + wn * 64 + nt * 8 + tig * 2;
            const float b0 = bias[n], b1 = bias[n + 1];
            float2 v0 = make_float2(acc[mt][nt][0] + b0, acc[mt][nt][1] + b1);
            float2 v1 = make_float2(acc[mt][nt][2] + b0, acc[mt][nt][3] + b1);
            *(float2*)(out + (size_t)m * N + n) = v0;
            *(float2*)(out + (size_t)(m + 8) * N + n) = v1;
        }
    }
}

// ---------------------------------------------------------------------------
__global__ void reset_kernel(int zero_h)
{
    int i = blockIdx.x * blockDim.x + threadIdx.x;
    if (i < 128) g_flags[i] = 0u;
    if (zero_h && i < B * H) g_h[0][i] = 0.f;
}

// ---------------------------------------------------------------------------
__device__ __forceinline__ float dot512(const float4* __restrict__ sW4,
                                        int row, int lane, const float4* h4)
{
    float s = 0.f;
#pragma unroll
    for (int i = 0; i < 4; i++) {
        float4 w = sW4[row * 128 + lane + 32 * i];
        s += h4[i].x * w.x + h4[i].y * w.y + h4[i].z * w.z + h4[i].w * w.w;
    }
#pragma unroll
    for (int off = 16; off > 0; off >>= 1)
        s += __shfl_xor_sync(0xffffffffu, s, off);
    return s;
}

// ---------------------------------------------------------------------------
// Persistent encoder scan
// ---------------------------------------------------------------------------
__global__ void __launch_bounds__(256) enc_scan(
    const float* __restrict__ gi, const float* __restrict__ Whh,
    const float* __restrict__ bhh, float* __restrict__ enc_out)
{
    __shared__ __align__(16) float sW[12 * 512];
    const int u0 = blockIdx.x * 4;
    for (int f = threadIdx.x; f < 12 * 512; f += 256) {
        int r = f >> 9, c = f & 511;
        sW[f] = Whh[(size_t)((r >> 2) * H + u0 + (r & 3)) * H + c];
    }
    __syncthreads();

    const float4* sW4 = (const float4*)sW;
    const int warp = threadIdx.x >> 5, lane = threadIdx.x & 31;
    unsigned epoch = 0;

    for (int t = 0; t < S; t++) {
        const float* hin = g_h[t & 1];
        float* hout = g_h[(t + 1) & 1];
        const float* gi_t = gi + (size_t)t * 3 * H;
#pragma unroll
        for (int bi = 0; bi < 4; bi++) {
            const int b = warp + bi * 8;
            const float4* hb4 = (const float4*)(hin + b * H);
            float4 h4[4];
#pragma unroll
            for (int i = 0; i < 4; i++) h4[i] = __ldcg(hb4 + lane + 32 * i);

            float dr = 0.f, dz = 0.f, dn = 0.f;
#pragma unroll
            for (int r = 0; r < 12; r++) {
                float s = dot512(sW4, r, lane, h4);
                if (r == lane)      dr = s;
                if (r == lane + 4)  dz = s;
                if (r == lane + 8)  dn = s;
            }
            if (lane < 4) {
                const int u = u0 + lane;
                const float* gib = gi_t + (size_t)b * (S * 3 * H);
                float ghr = dr + bhh[u];
                float ghz = dz + bhh[H + u];
                float ghn = dn + bhh[2 * H + u];
                float rr = sigf(gib[u] + ghr);
                float zz = sigf(gib[H + u] + ghz);
                float nn = tanhf(gib[2 * H + u] + rr * ghn);
                float hprev = __ldcg(hin + b * H + u);
                float hnew = (1.f - zz) * nn + zz * hprev;
                hout[b * H + u] = hnew;
                enc_out[((size_t)b * S + t) * H + u] = hnew;
            }
        }
        flag_bar(epoch);
    }
}

// ---------------------------------------------------------------------------
// Persistent decoder scan: 4 phases/step, flag barriers.
// Dynamic smem (floats):
//  sWh[6144] sWc[6144] sWq[2048] sv[512] shq[512] ssc[128] sred[16]
//  spart[1024]  (8 warps * 32 float4 = 256 float4 = 1024 floats)
//  total = 16528 floats
// ---------------------------------------------------------------------------
__global__ void __launch_bounds__(256) dec_scan(
    const float* __restrict__ giy,
    const float* __restrict__ Whh, const float* __restrict__ bhh,
    const float* __restrict__ Wih,
    const float* __restrict__ attnW, const float* __restrict__ attnv,
    const float* __restrict__ enc_out, const float* __restrict__ enc_proj,
    float* __restrict__ dec_out)
{
    extern __shared__ __align__(16) float sm[];
    float* sWh   = sm;            // 6144
    float* sWc   = sm + 6144;     // 6144
    float* sWq   = sm + 12288;    // 2048
    float* sv    = sm + 14336;    // 512
    float* shq   = sm + 14848;    // 512
    float* ssc   = sm + 15360;    // 128
    float* sred  = sm + 15488;    // 16
    float* spart = sm + 15504;    // 1024

    const int u0 = blockIdx.x * 4;
    const int warp = threadIdx.x >> 5, lane = threadIdx.x & 31;
    const int b_at = blockIdx.x & 31;
    const int squad = blockIdx.x >> 5;

    for (int f = threadIdx.x; f < 6144; f += 256) {
        int r = f >> 9, c = f & 511;
        int grow = (r >> 2) * H + u0 + (r & 3);
        sWh[f] = Whh[(size_t)grow * H + c];
        sWc[f] = Wih[(size_t)grow * (E + H) + E + c];
    }
    for (int f = threadIdx.x; f < 2048; f += 256) {
        int r = f >> 9, c = f & 511;
        sWq[f] = attnW[(size_t)(u0 + r) * (2 * H) + c];
    }
    for (int f = threadIdx.x; f < 512; f += 256) sv[f] = attnv[f];
    __syncthreads();

    const float4* sWh4 = (const float4*)sWh;
    const float4* sWc4 = (const float4*)sWc;
    const float4* sWq4 = (const float4*)sWq;
    const float4* sv4  = (const float4*)sv;
    const float4* shq4 = (const float4*)shq;
    unsigned epoch = 0;

    for (int t = 0; t < T; t++) {
        const float* hin = g_h[t & 1];
        float* hout = g_h[(t + 1) & 1];

        // ===== phase A: hq =====
#pragma unroll
        for (int bi = 0; bi < 4; bi++) {
            const int b = warp + bi * 8;
            const float4* hb4 = (const float4*)(hin + b * H);
            float4 h4[4];
#pragma unroll
            for (int i = 0; i < 4; i++) h4[i] = __ldcg(hb4 + lane + 32 * i);
            float mine = 0.f;
#pragma unroll
            for (int r = 0; r < 4; r++) {
                float s = dot512(sWq4, r, lane, h4);
                if (r == lane) mine = s;
            }
            if (lane < 4) g_hq[b * H + u0 + lane] = mine;
        }
        flag_bar(epoch);

        // ===== phase B: scores =====
        {
            float4* shqw = (float4*)shq;
            for (int f = threadIdx.x; f < 128; f += 256)
                shqw[f] = __ldcg((const float4*)&g_hq[b_at * H] + f);
        }
        __syncthreads();
#pragma unroll
        for (int c = 0; c < 4; c++) {
            const int s = squad * 32 + warp * 4 + c;
            const float4* eps4 = (const float4*)(enc_proj + ((size_t)b_at * S + s) * H);
            float e = 0.f;
#pragma unroll
            for (int i = 0; i < 4; i++) {
                float4 p = __ldg(eps4 + lane + 32 * i);
                float4 q = shq4[lane + 32 * i];
                float4 vv = sv4[lane + 32 * i];
                e += vv.x * tanh_fast(q.x + p.x);
                e += vv.y * tanh_fast(q.y + p.y);
                e += vv.z * tanh_fast(q.z + p.z);
                e += vv.w * tanh_fast(q.w + p.w);
            }
#pragma unroll
            for (int off = 16; off > 0; off >>= 1)
                e += __shfl_xor_sync(0xffffffffu, e, off);
            if (lane == 0) g_scores[b_at * S + s] = e;
        }
        flag_bar(epoch);

        // ===== phase C: softmax + ctx (u-slice squad*128, batch b_at) =====
        if (threadIdx.x < 128) {
            float v = __ldcg(&g_scores[b_at * S + threadIdx.x]);
            ssc[threadIdx.x] = v;
#pragma unroll
            for (int off = 16; off > 0; off >>= 1)
                v = fmaxf(v, __shfl_xor_sync(0xffffffffu, v, off));
            if (lane == 0) sred[warp] = v;
        }
        __syncthreads();
        {
            float smax = fmaxf(fmaxf(sred[0], sred[1]), fmaxf(sred[2], sred[3]));
            __syncthreads();
            if (threadIdx.x < 128) {
                float e = expf(ssc[threadIdx.x] - smax);
                ssc[threadIdx.x] = e;
#pragma unroll
                for (int off = 16; off > 0; off >>= 1)
                    e += __shfl_xor_sync(0xffffffffu, e, off);
                if (lane == 0) sred[4 + warp] = e;
            }
            __syncthreads();
            const float inv = 1.f / (sred[4] + sred[5] + sred[6] + sred[7]);

            // warp-partial weighted sum: warp covers s in [warp*16, +16)
            const float4* eo4 = (const float4*)(enc_out + (size_t)b_at * S * H);
            float4 a = make_float4(0.f, 0.f, 0.f, 0.f);
#pragma unroll
            for (int si = 0; si < 16; si++) {
                const int s = warp * 16 + si;
                const float wgt = ssc[s];
                float4 v = __ldg(eo4 + s * 128 + squad * 32 + lane);
                a.x += wgt * v.x; a.y += wgt * v.y;
                a.z += wgt * v.z; a.w += wgt * v.w;
            }
            ((float4*)spart)[warp * 32 + lane] = a;
            __syncthreads();
            if (threadIdx.x < 32) {
                float4 sum = make_float4(0.f, 0.f, 0.f, 0.f);
#pragma unroll
                for (int w = 0; w < 8; w++) {
                    float4 p = ((float4*)spart)[w * 32 + threadIdx.x];
                    sum.x += p.x; sum.y += p.y; sum.z += p.z; sum.w += p.w;
                }
                sum.x *= inv; sum.y *= inv; sum.z *= inv; sum.w *= inv;
                ((float4*)&g_ctx[b_at * H + squad * 128])[threadIdx.x] = sum;
            }
        }
        flag_bar(epoch);

        // ===== phase D: GRU =====
        const float* giy_t = giy + (size_t)t * 3 * H;
#pragma unroll
        for (int bi = 0; bi < 4; bi++) {
            const int b = warp + bi * 8;
            const float4* hb4 = (const float4*)(hin + b * H);
            const float4* cb4 = (const float4*)(g_ctx + b * H);
            float4 h4[4], c4[4];
#pragma unroll
            for (int i = 0; i < 4; i++) {
                h4[i] = __ldcg(hb4 + lane + 32 * i);
                c4[i] = __ldcg(cb4 + lane + 32 * i);
            }
            float dhr = 0.f, dhz = 0.f, dhn = 0.f;
            float dcr = 0.f, dcz = 0.f, dcn = 0.f;
#pragma unroll
            for (int r = 0; r < 12; r++) {
                float s1 = 0.f, s2 = 0.f;
#pragma unroll
                for (int i = 0; i < 4; i++) {
                    float4 wh = sWh4[r * 128 + lane + 32 * i];
                    float4 wc = sWc4[r * 128 + lane + 32 * i];
                    s1 += h4[i].x * wh.x + h4[i].y * wh.y + h4[i].z * wh.z + h4[i].w * wh.w;
                    s2 += c4[i].x * wc.x + c4[i].y * wc.y + c4[i].z * wc.z + c4[i].w * wc.w;
                }
#pragma unroll
                for (int off = 16; off > 0; off >>= 1) {
                    s1 += __shfl_xor_sync(0xffffffffu, s1, off);
                    s2 += __shfl_xor_sync(0xffffffffu, s2, off);
                }
                if (r == lane)      { dhr = s1; dcr = s2; }
                if (r == lane + 4)  { dhz = s1; dcz = s2; }
                if (r == lane + 8)  { dhn = s1; dcn = s2; }
            }
            if (lane < 4) {
                const int u = u0 + lane;
                const float* gy = giy_t + (size_t)b * (T * 3 * H);
                float gir = gy[u] + dcr;
                float giz = gy[H + u] + dcz;
                float gin = gy[2 * H + u] + dcn;
                float ghr = dhr + bhh[u];
                float ghz = dhz + bhh[H + u];
                float ghn = dhn + bhh[2 * H + u];
                float rr = sigf(gir + ghr);
                float zz = sigf(giz + ghz);
                float nn = tanhf(gin + rr * ghn);
                float hprev = __ldcg(hin + b * H + u);
                float hnew = (1.f - zz) * nn + zz * hprev;
                hout[b * H + u] = hnew;
                dec_out[((size_t)b * T + t) * H + u] = hnew;
            }
        }
        flag_bar(epoch);
    }
}

// ---------------------------------------------------------------------------
extern "C" void kernel_launch(void* const* d_in, const int* in_sizes, int n_in,
                              void* d_out, int out_size)
{
    const int*   src     = (const int*)  d_in[0];
    const int*   tgt     = (const int*)  d_in[1];
    const float* emb_src = (const float*)d_in[2];
    const float* emb_tgt = (const float*)d_in[3];
    const float* enc_Wih = (const float*)d_in[4];
    const float* enc_Whh = (const float*)d_in[5];
    const float* enc_bih = (const float*)d_in[6];
    const float* enc_bhh = (const float*)d_in[7];
    const float* dec_Wih = (const float*)d_in[8];
    const float* dec_Whh = (const float*)d_in[9];
    const float* dec_bih = (const float*)d_in[10];
    const float* dec_bhh = (const float*)d_in[11];
    const float* attn_W  = (const float*)d_in[12];
    const float* attn_b  = (const float*)d_in[13];
    const float* attn_v  = (const float*)d_in[14];
    const float* fc_W    = (const float*)d_in[15];
    const float* fc_b    = (const float*)d_in[16];
    float* logits = (float*)d_out;

    float *enc_gi, *dec_giy, *enc_out, *enc_proj, *dec_out;
    cudaGetSymbolAddress((void**)&enc_gi,  g_enc_gi);
    cudaGetSymbolAddress((void**)&dec_giy, g_dec_giy);
    cudaGetSymbolAddress((void**)&enc_out, g_enc_out);
    cudaGetSymbolAddress((void**)&enc_proj,g_enc_proj);
    cudaGetSymbolAddress((void**)&dec_out, g_dec_out);

    const int gemm_smem = 4 * BUFE * 4;
    const int dec_smem  = 16528 * 4;
    static int smem_set = 0;
    if (!smem_set) {
        cudaFuncSetAttribute(dec_scan,
            cudaFuncAttributeMaxDynamicSharedMemorySize, dec_smem);
        cudaFuncSetAttribute(gemm_tf32,
            cudaFuncAttributeMaxDynamicSharedMemorySize, gemm_smem);
        smem_set = 1;
    }

    gemm_tf32<<<dim3(3 * H / 128, B * S / 128), 256, gemm_smem>>>(
        emb_src, E, src, enc_Wih, E, enc_bih, enc_gi, 3 * H, E);
    gemm_tf32<<<dim3(3 * H / 128, B * T / 128), 256, gemm_smem>>>(
        emb_tgt, E, tgt, dec_Wih, E + H, dec_bih, dec_giy, 3 * H, E);

    reset_kernel<<<(B * H + 255) / 256, 256>>>(1);

    enc_scan<<<128, 256>>>(enc_gi, enc_Whh, enc_bhh, enc_out);

    gemm_tf32<<<dim3(H / 128, B * S / 128), 256, gemm_smem>>>(
        enc_out, H, nullptr, attn_W + H, 2 * H, attn_b, enc_proj, H, H);

    reset_kernel<<<1, 128>>>(0);

    dec_scan<<<128, 256, dec_smem>>>(
        dec_giy, dec_Whh, dec_bhh, dec_Wih,
        attn_W, attn_v, enc_out, enc_proj, dec_out);

    gemm_tf32<<<dim3(VT / 128, B * T / 128), 256, gemm_smem>>>(
        dec_out, H, nullptr, fc_W, H, fc_b, logits, VT, H);
}

// round 11
// speedup vs baseline: 1.7281x; 1.7281x over previous
#include <cuda_runtime.h>
#include <cuda_fp16.h>
#include <math.h>
#include <stdint.h>

#define B   32
#define S   128
#define T   128
#define E   256
#define H   512
#define VT  16000

// ---------------------------------------------------------------------------
__device__ float g_enc_gi [B * S * 3 * H];
__device__ float g_dec_giy[B * T * 3 * H];
__device__ float g_enc_out[B * S * H];
__device__ float g_enc_proj[B * S * H];
__device__ float g_dec_out[B * T * H];
__device__ float g_h[2][B * H];
__device__ float g_hq[B * H];
__device__ float g_scores[B * S];
__device__ float g_ctx[B * H];
__device__ unsigned g_bar;

__device__ __forceinline__ float sigf(float x) { return 1.f / (1.f + expf(-x)); }
__device__ __forceinline__ uint32_t f2tf32(float x) {
    uint32_t u; asm("cvt.rna.tf32.f32 %0, %1;" : "=r"(u) : "f"(x)); return u;
}
// pack two f32 -> f16x2 (hi, lo), tanh both halves in one MUFU op
__device__ __forceinline__ uint32_t pack_h2(float hi, float lo) {
    uint32_t r; asm("cvt.rn.f16x2.f32 %0, %1, %2;" : "=r"(r) : "f"(hi), "f"(lo));
    return r;
}
__device__ __forceinline__ uint32_t tanh_h2(uint32_t x) {
    uint32_t r; asm("tanh.approx.f16x2 %0, %1;" : "=r"(r) : "r"(x));
    return r;
}

// Grid barrier (R6 proven-best): single release-reduction + acquire poll.
__device__ __forceinline__ void grid_bar(unsigned& target) {
    target += gridDim.x;
    __syncthreads();
    if (threadIdx.x == 0) {
        asm volatile("red.release.gpu.add.u32 [%0], 1;" :: "l"(&g_bar) : "memory");
        unsigned v;
        do {
            asm volatile("ld.acquire.gpu.u32 %0, [%1];" : "=r"(v) : "l"(&g_bar) : "memory");
        } while (v < target);
    }
    __syncthreads();
}

// ---------------------------------------------------------------------------
// TF32 tensor-core GEMM
// ---------------------------------------------------------------------------
#define KT   32
#define LDS_ 36
#define BUFE (128 * LDS_)

__global__ void __launch_bounds__(256, 2) gemm_tf32(
    const float* __restrict__ A, int lda, const int* __restrict__ idx,
    const float* __restrict__ W, int ldw,
    const float* __restrict__ bias,
    float* __restrict__ out, int N, int K)
{
    extern __shared__ uint32_t smem_u[];
    uint32_t* As = smem_u;
    uint32_t* Bs = smem_u + 2 * BUFE;

    const int tid = threadIdx.x;
    const int m0 = blockIdx.y * 128, n0 = blockIdx.x * 128;
    const int warp = tid >> 5, lane = tid & 31;
    const int gid = lane >> 2, tig = lane & 3;
    const int wm = warp >> 1, wn = warp & 1;

    const int lrow = tid >> 3, lk = (tid & 7) * 4;
    const float* aptr[4];
    const float* bptr[4];
#pragma unroll
    for (int i = 0; i < 4; i++) {
        int m = m0 + lrow + i * 32;
        int r = idx ? idx[m] : m;
        aptr[i] = A + (size_t)r * lda + lk;
        bptr[i] = W + (size_t)(n0 + lrow + i * 32) * ldw + lk;
    }
    const int sst = lrow * LDS_ + lk;

    float acc[2][8][4];
#pragma unroll
    for (int mt = 0; mt < 2; mt++)
#pragma unroll
        for (int nt = 0; nt < 8; nt++)
#pragma unroll
            for (int c = 0; c < 4; c++) acc[mt][nt][c] = 0.f;

    const int nk = K / KT;
    float4 av[4], bv[4];

#pragma unroll
    for (int i = 0; i < 4; i++) {
        av[i] = *(const float4*)(aptr[i]);
        bv[i] = *(const float4*)(bptr[i]);
    }
#pragma unroll
    for (int i = 0; i < 4; i++) {
        uint32_t* a = As + sst + i * 32 * LDS_;
        a[0] = f2tf32(av[i].x); a[1] = f2tf32(av[i].y);
        a[2] = f2tf32(av[i].z); a[3] = f2tf32(av[i].w);
        uint32_t* b = Bs + sst + i * 32 * LDS_;
        b[0] = f2tf32(bv[i].x); b[1] = f2tf32(bv[i].y);
        b[2] = f2tf32(bv[i].z); b[3] = f2tf32(bv[i].w);
    }
    __syncthreads();

    for (int kt = 0; kt < nk; kt++) {
        if (kt + 1 < nk) {
            const int off = (kt + 1) * KT;
#pragma unroll
            for (int i = 0; i < 4; i++) {
                av[i] = *(const float4*)(aptr[i] + off);
                bv[i] = *(const float4*)(bptr[i] + off);
            }
        }

        const uint32_t* Ab = As + (kt & 1) * BUFE + wm * 32 * LDS_;
        const uint32_t* Bb = Bs + (kt & 1) * BUFE + wn * 64 * LDS_;
#pragma unroll
        for (int k8 = 0; k8 < 4; k8++) {
            const int kc = k8 * 8 + tig;
            uint32_t af[2][4], bf[8][2];
#pragma unroll
            for (int mt = 0; mt < 2; mt++) {
                const uint32_t* p = Ab + (mt * 16 + gid) * LDS_ + kc;
                af[mt][0] = p[0];
                af[mt][1] = p[8 * LDS_];
                af[mt][2] = p[4];
                af[mt][3] = p[8 * LDS_ + 4];
            }
#pragma unroll
            for (int nt = 0; nt < 8; nt++) {
                const uint32_t* p = Bb + (nt * 8 + gid) * LDS_ + kc;
                bf[nt][0] = p[0];
                bf[nt][1] = p[4];
            }
#pragma unroll
            for (int mt = 0; mt < 2; mt++)
#pragma unroll
                for (int nt = 0; nt < 8; nt++) {
                    float* c = acc[mt][nt];
                    asm volatile(
                        "mma.sync.aligned.m16n8k8.row.col.f32.tf32.tf32.f32 "
                        "{%0,%1,%2,%3}, {%4,%5,%6,%7}, {%8,%9}, {%0,%1,%2,%3};"
                        : "+f"(c[0]), "+f"(c[1]), "+f"(c[2]), "+f"(c[3])
                        : "r"(af[mt][0]), "r"(af[mt][1]), "r"(af[mt][2]), "r"(af[mt][3]),
                          "r"(bf[nt][0]), "r"(bf[nt][1]));
                }
        }

        if (kt + 1 < nk) {
            const int bsel = (kt + 1) & 1;
#pragma unroll
            for (int i = 0; i < 4; i++) {
                uint32_t* a = As + bsel * BUFE + sst + i * 32 * LDS_;
                a[0] = f2tf32(av[i].x); a[1] = f2tf32(av[i].y);
                a[2] = f2tf32(av[i].z); a[3] = f2tf32(av[i].w);
                uint32_t* b = Bs + bsel * BUFE + sst + i * 32 * LDS_;
                b[0] = f2tf32(bv[i].x); b[1] = f2tf32(bv[i].y);
                b[2] = f2tf32(bv[i].z); b[3] = f2tf32(bv[i].w);
            }
            __syncthreads();
        }
    }

#pragma unroll
    for (int mt = 0; mt < 2; mt++) {
        const int m = m0 + wm * 32 + mt * 16 + gid;
#pragma unroll
        for (int nt = 0; nt < 8; nt++) {
            const int n = n0 + wn * 64 + nt * 8 + tig * 2;
            const float b0 = bias[n], b1 = bias[n + 1];
            float2 v0 = make_float2(acc[mt][nt][0] + b0, acc[mt][nt][1] + b1);
            float2 v1 = make_float2(acc[mt][nt][2] + b0, acc[mt][nt][3] + b1);
            *(float2*)(out + (size_t)m * N + n) = v0;
            *(float2*)(out + (size_t)(m + 8) * N + n) = v1;
        }
    }
}

// ---------------------------------------------------------------------------
__global__ void reset_kernel(int zero_h)
{
    int i = blockIdx.x * blockDim.x + threadIdx.x;
    if (i == 0) g_bar = 0u;
    if (zero_h && i < B * H) g_h[0][i] = 0.f;
}

// ---------------------------------------------------------------------------
__device__ __forceinline__ float dot512(const float4* __restrict__ sW4,
                                        int row, int lane, const float4* h4)
{
    float s = 0.f;
#pragma unroll
    for (int i = 0; i < 4; i++) {
        float4 w = sW4[row * 128 + lane + 32 * i];
        s += h4[i].x * w.x + h4[i].y * w.y + h4[i].z * w.z + h4[i].w * w.w;
    }
#pragma unroll
    for (int off = 16; off > 0; off >>= 1)
        s += __shfl_xor_sync(0xffffffffu, s, off);
    return s;
}

// ---------------------------------------------------------------------------
// Persistent encoder scan
// ---------------------------------------------------------------------------
__global__ void __launch_bounds__(256) enc_scan(
    const float* __restrict__ gi, const float* __restrict__ Whh,
    const float* __restrict__ bhh, float* __restrict__ enc_out)
{
    __shared__ __align__(16) float sW[12 * 512];
    const int u0 = blockIdx.x * 4;
    for (int f = threadIdx.x; f < 12 * 512; f += 256) {
        int r = f >> 9, c = f & 511;
        sW[f] = Whh[(size_t)((r >> 2) * H + u0 + (r & 3)) * H + c];
    }
    __syncthreads();

    const float4* sW4 = (const float4*)sW;
    const int warp = threadIdx.x >> 5, lane = threadIdx.x & 31;
    unsigned target = 0;

    for (int t = 0; t < S; t++) {
        const float* hin = g_h[t & 1];
        float* hout = g_h[(t + 1) & 1];
        const float* gi_t = gi + (size_t)t * 3 * H;
#pragma unroll
        for (int bi = 0; bi < 4; bi++) {
            const int b = warp + bi * 8;
            const float4* hb4 = (const float4*)(hin + b * H);
            float4 h4[4];
#pragma unroll
            for (int i = 0; i < 4; i++) h4[i] = __ldcg(hb4 + lane + 32 * i);

            float dr = 0.f, dz = 0.f, dn = 0.f;
#pragma unroll
            for (int r = 0; r < 12; r++) {
                float s = dot512(sW4, r, lane, h4);
                if (r == lane)      dr = s;
                if (r == lane + 4)  dz = s;
                if (r == lane + 8)  dn = s;
            }
            if (lane < 4) {
                const int u = u0 + lane;
                const float* gib = gi_t + (size_t)b * (S * 3 * H);
                float ghr = dr + bhh[u];
                float ghz = dz + bhh[H + u];
                float ghn = dn + bhh[2 * H + u];
                float rr = sigf(gib[u] + ghr);
                float zz = sigf(gib[H + u] + ghz);
                float nn = tanhf(gib[2 * H + u] + rr * ghn);
                float hprev = __ldcg(hin + b * H + u);
                float hnew = (1.f - zz) * nn + zz * hprev;
                hout[b * H + u] = hnew;
                enc_out[((size_t)b * S + t) * H + u] = hnew;
            }
        }
        grid_bar(target);
    }
}

// ---------------------------------------------------------------------------
// Persistent decoder scan: 4 phases/step.
// Phase B uses tanh.approx.f16x2 (2 tanh per MUFU op).
// Dynamic smem (floats): 16528 total.
// ---------------------------------------------------------------------------
__global__ void __launch_bounds__(256) dec_scan(
    const float* __restrict__ giy,
    const float* __restrict__ Whh, const float* __restrict__ bhh,
    const float* __restrict__ Wih,
    const float* __restrict__ attnW, const float* __restrict__ attnv,
    const float* __restrict__ enc_out, const float* __restrict__ enc_proj,
    float* __restrict__ dec_out)
{
    extern __shared__ __align__(16) float sm[];
    float* sWh   = sm;            // 6144
    float* sWc   = sm + 6144;     // 6144
    float* sWq   = sm + 12288;    // 2048
    float* sv    = sm + 14336;    // 512
    float* shq   = sm + 14848;    // 512
    float* ssc   = sm + 15360;    // 128
    float* sred  = sm + 15488;    // 16
    float* spart = sm + 15504;    // 1024

    const int u0 = blockIdx.x * 4;
    const int warp = threadIdx.x >> 5, lane = threadIdx.x & 31;
    const int b_at = blockIdx.x & 31;
    const int squad = blockIdx.x >> 5;

    for (int f = threadIdx.x; f < 6144; f += 256) {
        int r = f >> 9, c = f & 511;
        int grow = (r >> 2) * H + u0 + (r & 3);
        sWh[f] = Whh[(size_t)grow * H + c];
        sWc[f] = Wih[(size_t)grow * (E + H) + E + c];
    }
    for (int f = threadIdx.x; f < 2048; f += 256) {
        int r = f >> 9, c = f & 511;
        sWq[f] = attnW[(size_t)(u0 + r) * (2 * H) + c];
    }
    for (int f = threadIdx.x; f < 512; f += 256) sv[f] = attnv[f];
    __syncthreads();

    const float4* sWh4 = (const float4*)sWh;
    const float4* sWc4 = (const float4*)sWc;
    const float4* sWq4 = (const float4*)sWq;
    const float4* sv4  = (const float4*)sv;
    const float4* shq4 = (const float4*)shq;
    unsigned target = 0;

    for (int t = 0; t < T; t++) {
        const float* hin = g_h[t & 1];
        float* hout = g_h[(t + 1) & 1];

        // ===== phase A: hq =====
#pragma unroll
        for (int bi = 0; bi < 4; bi++) {
            const int b = warp + bi * 8;
            const float4* hb4 = (const float4*)(hin + b * H);
            float4 h4[4];
#pragma unroll
            for (int i = 0; i < 4; i++) h4[i] = __ldcg(hb4 + lane + 32 * i);
            float mine = 0.f;
#pragma unroll
            for (int r = 0; r < 4; r++) {
                float s = dot512(sWq4, r, lane, h4);
                if (r == lane) mine = s;
            }
            if (lane < 4) g_hq[b * H + u0 + lane] = mine;
        }
        grid_bar(target);

        // ===== phase B: scores (f16x2 tanh, 2 per MUFU) =====
        {
            float4* shqw = (float4*)shq;
            for (int f = threadIdx.x; f < 128; f += 256)
                shqw[f] = __ldcg((const float4*)&g_hq[b_at * H] + f);
        }
        __syncthreads();
#pragma unroll
        for (int c = 0; c < 4; c++) {
            const int s = squad * 32 + warp * 4 + c;
            const float4* eps4 = (const float4*)(enc_proj + ((size_t)b_at * S + s) * H);
            float e = 0.f;
#pragma unroll
            for (int i = 0; i < 4; i++) {
                float4 p = __ldg(eps4 + lane + 32 * i);
                float4 q = shq4[lane + 32 * i];
                float4 vv = sv4[lane + 32 * i];
                uint32_t pa = tanh_h2(pack_h2(q.y + p.y, q.x + p.x));
                uint32_t pb = tanh_h2(pack_h2(q.w + p.w, q.z + p.z));
                __half2 ta = *reinterpret_cast<__half2*>(&pa);
                __half2 tb = *reinterpret_cast<__half2*>(&pb);
                e += vv.x * __low2float(ta);
                e += vv.y * __high2float(ta);
                e += vv.z * __low2float(tb);
                e += vv.w * __high2float(tb);
            }
#pragma unroll
            for (int off = 16; off > 0; off >>= 1)
                e += __shfl_xor_sync(0xffffffffu, e, off);
            if (lane == 0) g_scores[b_at * S + s] = e;
        }
        grid_bar(target);

        // ===== phase C: softmax + ctx (coalesced warp-partial) =====
        if (threadIdx.x < 128) {
            float v = __ldcg(&g_scores[b_at * S + threadIdx.x]);
            ssc[threadIdx.x] = v;
#pragma unroll
            for (int off = 16; off > 0; off >>= 1)
                v = fmaxf(v, __shfl_xor_sync(0xffffffffu, v, off));
            if (lane == 0) sred[warp] = v;
        }
        __syncthreads();
        {
            float smax = fmaxf(fmaxf(sred[0], sred[1]), fmaxf(sred[2], sred[3]));
            __syncthreads();
            if (threadIdx.x < 128) {
                float e = expf(ssc[threadIdx.x] - smax);
                ssc[threadIdx.x] = e;
#pragma unroll
                for (int off = 16; off > 0; off >>= 1)
                    e += __shfl_xor_sync(0xffffffffu, e, off);
                if (lane == 0) sred[4 + warp] = e;
            }
            __syncthreads();
            const float inv = 1.f / (sred[4] + sred[5] + sred[6] + sred[7]);

            const float4* eo4 = (const float4*)(enc_out + (size_t)b_at * S * H);
            float4 a = make_float4(0.f, 0.f, 0.f, 0.f);
#pragma unroll
            for (int si = 0; si < 16; si++) {
                const int s = warp * 16 + si;
                const float wgt = ssc[s];
                float4 v = __ldg(eo4 + s * 128 + squad * 32 + lane);
                a.x += wgt * v.x; a.y += wgt * v.y;
                a.z += wgt * v.z; a.w += wgt * v.w;
            }
            ((float4*)spart)[warp * 32 + lane] = a;
            __syncthreads();
            if (threadIdx.x < 32) {
                float4 sum = make_float4(0.f, 0.f, 0.f, 0.f);
#pragma unroll
                for (int w = 0; w < 8; w++) {
                    float4 p = ((float4*)spart)[w * 32 + threadIdx.x];
                    sum.x += p.x; sum.y += p.y; sum.z += p.z; sum.w += p.w;
                }
                sum.x *= inv; sum.y *= inv; sum.z *= inv; sum.w *= inv;
                ((float4*)&g_ctx[b_at * H + squad * 128])[threadIdx.x] = sum;
            }
        }
        grid_bar(target);

        // ===== phase D: GRU =====
        const float* giy_t = giy + (size_t)t * 3 * H;
#pragma unroll
        for (int bi = 0; bi < 4; bi++) {
            const int b = warp + bi * 8;
            const float4* hb4 = (const float4*)(hin + b * H);
            const float4* cb4 = (const float4*)(g_ctx + b * H);
            float4 h4[4], c4[4];
#pragma unroll
            for (int i = 0; i < 4; i++) {
                h4[i] = __ldcg(hb4 + lane + 32 * i);
                c4[i] = __ldcg(cb4 + lane + 32 * i);
            }
            float dhr = 0.f, dhz = 0.f, dhn = 0.f;
            float dcr = 0.f, dcz = 0.f, dcn = 0.f;
#pragma unroll
            for (int r = 0; r < 12; r++) {
                float s1 = 0.f, s2 = 0.f;
#pragma unroll
                for (int i = 0; i < 4; i++) {
                    float4 wh = sWh4[r * 128 + lane + 32 * i];
                    float4 wc = sWc4[r * 128 + lane + 32 * i];
                    s1 += h4[i].x * wh.x + h4[i].y * wh.y + h4[i].z * wh.z + h4[i].w * wh.w;
                    s2 += c4[i].x * wc.x + c4[i].y * wc.y + c4[i].z * wc.z + c4[i].w * wc.w;
                }
#pragma unroll
                for (int off = 16; off > 0; off >>= 1) {
                    s1 += __shfl_xor_sync(0xffffffffu, s1, off);
                    s2 += __shfl_xor_sync(0xffffffffu, s2, off);
                }
                if (r == lane)      { dhr = s1; dcr = s2; }
                if (r == lane + 4)  { dhz = s1; dcz = s2; }
                if (r == lane + 8)  { dhn = s1; dcn = s2; }
            }
            if (lane < 4) {
                const int u = u0 + lane;
                const float* gy = giy_t + (size_t)b * (T * 3 * H);
                float gir = gy[u] + dcr;
                float giz = gy[H + u] + dcz;
                float gin = gy[2 * H + u] + dcn;
                float ghr = dhr + bhh[u];
                float ghz = dhz + bhh[H + u];
                float ghn = dhn + bhh[2 * H + u];
                float rr = sigf(gir + ghr);
                float zz = sigf(giz + ghz);
                float nn = tanhf(gin + rr * ghn);
                float hprev = __ldcg(hin + b * H + u);
                float hnew = (1.f - zz) * nn + zz * hprev;
                hout[b * H + u] = hnew;
                dec_out[((size_t)b * T + t) * H + u] = hnew;
            }
        }
        grid_bar(target);
    }
}

// ---------------------------------------------------------------------------
extern "C" void kernel_launch(void* const* d_in, const int* in_sizes, int n_in,
                              void* d_out, int out_size)
{
    const int*   src     = (const int*)  d_in[0];
    const int*   tgt     = (const int*)  d_in[1];
    const float* emb_src = (const float*)d_in[2];
    const float* emb_tgt = (const float*)d_in[3];
    const float* enc_Wih = (const float*)d_in[4];
    const float* enc_Whh = (const float*)d_in[5];
    const float* enc_bih = (const float*)d_in[6];
    const float* enc_bhh = (const float*)d_in[7];
    const float* dec_Wih = (const float*)d_in[8];
    const float* dec_Whh = (const float*)d_in[9];
    const float* dec_bih = (const float*)d_in[10];
    const float* dec_bhh = (const float*)d_in[11];
    const float* attn_W  = (const float*)d_in[12];
    const float* attn_b  = (const float*)d_in[13];
    const float* attn_v  = (const float*)d_in[14];
    const float* fc_W    = (const float*)d_in[15];
    const float* fc_b    = (const float*)d_in[16];
    float* logits = (float*)d_out;

    float *enc_gi, *dec_giy, *enc_out, *enc_proj, *dec_out;
    cudaGetSymbolAddress((void**)&enc_gi,  g_enc_gi);
    cudaGetSymbolAddress((void**)&dec_giy, g_dec_giy);
    cudaGetSymbolAddress((void**)&enc_out, g_enc_out);
    cudaGetSymbolAddress((void**)&enc_proj,g_enc_proj);
    cudaGetSymbolAddress((void**)&dec_out, g_dec_out);

    const int gemm_smem = 4 * BUFE * 4;
    const int dec_smem  = 16528 * 4;
    static int smem_set = 0;
    if (!smem_set) {
        cudaFuncSetAttribute(dec_scan,
            cudaFuncAttributeMaxDynamicSharedMemorySize, dec_smem);
        cudaFuncSetAttribute(gemm_tf32,
            cudaFuncAttributeMaxDynamicSharedMemorySize, gemm_smem);
        smem_set = 1;
    }

    gemm_tf32<<<dim3(3 * H / 128, B * S / 128), 256, gemm_smem>>>(
        emb_src, E, src, enc_Wih, E, enc_bih, enc_gi, 3 * H, E);
    gemm_tf32<<<dim3(3 * H / 128, B * T / 128), 256, gemm_smem>>>(
        emb_tgt, E, tgt, dec_Wih, E + H, dec_bih, dec_giy, 3 * H, E);

    reset_kernel<<<(B * H + 255) / 256, 256>>>(1);

    enc_scan<<<128, 256>>>(enc_gi, enc_Whh, enc_bhh, enc_out);

    gemm_tf32<<<dim3(H / 128, B * S / 128), 256, gemm_smem>>>(
        enc_out, H, nullptr, attn_W + H, 2 * H, attn_b, enc_proj, H, H);

    reset_kernel<<<1, 128>>>(0);

    dec_scan<<<128, 256, dec_smem>>>(
        dec_giy, dec_Whh, dec_bhh, dec_Wih,
        attn_W, attn_v, enc_out, enc_proj, dec_out);

    gemm_tf32<<<dim3(VT / 128, B * T / 128), 256, gemm_smem>>>(
        dec_out, H, nullptr, fc_W, H, fc_b, logits, VT, H);
}